// round 4
// baseline (speedup 1.0000x reference)
#include <cuda_runtime.h>
#include <cstdint>

#define F_IN 256
#define F_OUT 64
#define MAX_N 100000
#define MAX_E 3200000

// Scratch (device globals — no allocation allowed)
__device__ float g_h[(size_t)MAX_N * F_OUT];
__device__ float g_s1[MAX_N];
__device__ float g_s2[MAX_N];
__device__ int   g_deg[MAX_N];
__device__ int   g_rowptr[MAX_N + 1];
__device__ int   g_woff[MAX_N];
__device__ int   g_sdst[MAX_E];
__device__ int   g_bsum[128];
__device__ int   g_is64;

// ---------------------------------------------------------------------------
// Detect edge_index dtype: int64 (odd 32-bit words all zero) vs int32.
// Values are node ids < 100000 << 2^31, so int64 high words are 0.
// ---------------------------------------------------------------------------
__global__ void detect_kernel(const int* __restrict__ ei32) {
    int is64 = 1;
    for (int i = 0; i < 64; i++)
        if (ei32[2 * i + 1] != 0) { is64 = 0; break; }
    g_is64 = is64;
}

__device__ __forceinline__ int edge_at(const int* ei32, int is64, long long idx) {
    return is64 ? ei32[2 * idx] : ei32[idx];   // little-endian low word
}

// ---------------------------------------------------------------------------
__global__ void zero_deg_kernel(int n) {
    int i = blockIdx.x * blockDim.x + threadIdx.x;
    if (i < n) g_deg[i] = 0;
}

// ---------------------------------------------------------------------------
// SGEMM: h[M,64] = X[M,256] @ W[256,64]
// Block: 128 rows x 64 cols, 256 threads, each thread 8x4 outputs, KT=32.
// ---------------------------------------------------------------------------
__global__ void gemm_kernel(const float* __restrict__ X, const float* __restrict__ W, int M) {
    __shared__ __align__(16) float Xs[32][132];
    __shared__ __align__(16) float Ws[32][64];

    int tid = threadIdx.x;
    int tx = tid & 15;
    int ty = tid >> 4;
    int m0 = blockIdx.x * 128;

    float acc[8][4];
#pragma unroll
    for (int i = 0; i < 8; i++)
#pragma unroll
        for (int j = 0; j < 4; j++) acc[i][j] = 0.0f;

    for (int k0 = 0; k0 < F_IN; k0 += 32) {
#pragma unroll
        for (int i = 0; i < 4; i++) {
            int idx = tid + i * 256;
            int r   = idx >> 3;
            int kc  = idx & 7;
            float4 v = make_float4(0.f, 0.f, 0.f, 0.f);
            int row = m0 + r;
            if (row < M)
                v = *(const float4*)(X + (size_t)row * F_IN + k0 + kc * 4);
            Xs[kc * 4 + 0][r] = v.x;
            Xs[kc * 4 + 1][r] = v.y;
            Xs[kc * 4 + 2][r] = v.z;
            Xs[kc * 4 + 3][r] = v.w;
        }
#pragma unroll
        for (int i = 0; i < 2; i++) {
            int idx = tid + i * 256;
            int kr  = idx >> 4;
            int c4  = idx & 15;
            float4 w = *(const float4*)(W + (size_t)(k0 + kr) * F_OUT + c4 * 4);
            *(float4*)&Ws[kr][c4 * 4] = w;
        }
        __syncthreads();

#pragma unroll
        for (int kk = 0; kk < 32; kk++) {
            float4 b  = *(const float4*)&Ws[kk][tx * 4];
            float4 a0 = *(const float4*)&Xs[kk][ty * 8];
            float4 a1 = *(const float4*)&Xs[kk][ty * 8 + 4];
            float av[8] = {a0.x, a0.y, a0.z, a0.w, a1.x, a1.y, a1.z, a1.w};
            float bv[4] = {b.x, b.y, b.z, b.w};
#pragma unroll
            for (int i = 0; i < 8; i++)
#pragma unroll
                for (int j = 0; j < 4; j++)
                    acc[i][j] = fmaf(av[i], bv[j], acc[i][j]);
        }
        __syncthreads();
    }

#pragma unroll
    for (int i = 0; i < 8; i++) {
        int row = m0 + ty * 8 + i;
        if (row < M)
            *(float4*)(g_h + (size_t)row * F_OUT + tx * 4) =
                make_float4(acc[i][0], acc[i][1], acc[i][2], acc[i][3]);
    }
}

// ---------------------------------------------------------------------------
// s1 = h @ a[0:64], s2 = h @ a[64:128].  One warp per row.
// ---------------------------------------------------------------------------
__global__ void s_kernel(const float* __restrict__ a, int M) {
    int warp = (blockIdx.x * blockDim.x + threadIdx.x) >> 5;
    int lane = threadIdx.x & 31;
    if (warp >= M) return;
    const float* hr = g_h + (size_t)warp * F_OUT;
    float h0 = hr[lane], h1 = hr[lane + 32];
    float p1 = h0 * a[lane]      + h1 * a[lane + 32];
    float p2 = h0 * a[64 + lane] + h1 * a[96 + lane];
#pragma unroll
    for (int o = 16; o > 0; o >>= 1) {
        p1 += __shfl_xor_sync(0xffffffffu, p1, o);
        p2 += __shfl_xor_sync(0xffffffffu, p2, o);
    }
    if (lane == 0) { g_s1[warp] = p1; g_s2[warp] = p2; }
}

// ---------------------------------------------------------------------------
// CSR build: histogram -> scan -> scatter  (src/dst bounds-guarded: never trap)
// ---------------------------------------------------------------------------
__global__ void hist_kernel(const int* __restrict__ ei32, int E, int M) {
    int e = blockIdx.x * blockDim.x + threadIdx.x;
    if (e >= E) return;
    int is64 = g_is64;
    int src = edge_at(ei32, is64, e);
    if ((unsigned)src < (unsigned)M) atomicAdd(&g_deg[src], 1);
}

// Block-wise inclusive scan: 1024 elems/block, writes rowptr[i+1] (local incl)
__global__ void scan1_kernel(int n) {
    __shared__ int s[1024];
    int i = blockIdx.x * 1024 + threadIdx.x;
    int v = (i < n) ? g_deg[i] : 0;
    s[threadIdx.x] = v;
    __syncthreads();
#pragma unroll
    for (int o = 1; o < 1024; o <<= 1) {
        int t = (threadIdx.x >= o) ? s[threadIdx.x - o] : 0;
        __syncthreads();
        s[threadIdx.x] += t;
        __syncthreads();
    }
    if (i < n) g_rowptr[i + 1] = s[threadIdx.x];
    if (threadIdx.x == 1023) g_bsum[blockIdx.x] = s[1023];
}

// Exclusive scan of the (<=128) block sums, single block of 128 threads
__global__ void scan2_kernel(int nb) {
    __shared__ int s[128];
    int v = (threadIdx.x < nb) ? g_bsum[threadIdx.x] : 0;
    s[threadIdx.x] = v;
    __syncthreads();
#pragma unroll
    for (int o = 1; o < 128; o <<= 1) {
        int t = (threadIdx.x >= o) ? s[threadIdx.x - o] : 0;
        __syncthreads();
        s[threadIdx.x] += t;
        __syncthreads();
    }
    if (threadIdx.x < nb) g_bsum[threadIdx.x] = s[threadIdx.x] - v;
}

// Add block offsets; derive write cursors woff[i] = rowptr[i]
__global__ void scan3_kernel(int n) {
    int i = blockIdx.x * blockDim.x + threadIdx.x;
    if (i < n) {
        int val = g_rowptr[i + 1] + g_bsum[i >> 10];
        g_rowptr[i + 1] = val;
        g_woff[i] = val - g_deg[i];
    }
    if (i == 0) g_rowptr[0] = 0;
}

__global__ void scatter_kernel(const int* __restrict__ ei32, int E, int M) {
    int e = blockIdx.x * blockDim.x + threadIdx.x;
    if (e >= E) return;
    int is64 = g_is64;
    int src = edge_at(ei32, is64, e);
    int dst = edge_at(ei32, is64, (long long)E + e);
    if ((unsigned)src >= (unsigned)M || (unsigned)dst >= (unsigned)M) return;
    int pos = atomicAdd(&g_woff[src], 1);
    if ((unsigned)pos < (unsigned)MAX_E) g_sdst[pos] = dst;
}

// ---------------------------------------------------------------------------
// Aggregate + finalize: one warp per node. 8 lanes per edge (8 feats/lane),
// 4 edges in flight per warp. No atomics; fused rowsum-divide + ELU.
// w = exp(lrelu(s1[src]+s2[dst]))   (global-max subtraction cancels; skipped)
// ---------------------------------------------------------------------------
__global__ void aggregate_kernel(float* __restrict__ out, int M) {
    int node = (blockIdx.x * blockDim.x + threadIdx.x) >> 5;
    if (node >= M) return;
    int lane = threadIdx.x & 31;
    int sub  = lane & 7;    // feature group: features sub*8 .. sub*8+7
    int eg   = lane >> 3;   // edge group 0..3

    int beg = g_rowptr[node];
    int end = g_rowptr[node + 1];
    float s1v = g_s1[node];

    float acc[8];
#pragma unroll
    for (int j = 0; j < 8; j++) acc[j] = 0.0f;
    float wsum = 0.0f;

    for (int p = beg + eg; p < end; p += 4) {
        int dst = g_sdst[p];
        float v  = s1v + g_s2[dst];
        float ev = v > 0.0f ? v : 0.2f * v;
        float w  = __expf(ev);
        wsum += w;

        const float4* hv = (const float4*)(g_h + (size_t)dst * F_OUT);
        float4 p0 = hv[sub * 2];
        float4 p1 = hv[sub * 2 + 1];
        acc[0] = fmaf(w, p0.x, acc[0]);
        acc[1] = fmaf(w, p0.y, acc[1]);
        acc[2] = fmaf(w, p0.z, acc[2]);
        acc[3] = fmaf(w, p0.w, acc[3]);
        acc[4] = fmaf(w, p1.x, acc[4]);
        acc[5] = fmaf(w, p1.y, acc[5]);
        acc[6] = fmaf(w, p1.z, acc[6]);
        acc[7] = fmaf(w, p1.w, acc[7]);
    }

    // Reduce across the 4 edge groups (same sub lanes hold same features)
#pragma unroll
    for (int j = 0; j < 8; j++) {
        acc[j] += __shfl_xor_sync(0xffffffffu, acc[j], 8);
        acc[j] += __shfl_xor_sync(0xffffffffu, acc[j], 16);
    }
    wsum += __shfl_xor_sync(0xffffffffu, wsum, 8);
    wsum += __shfl_xor_sync(0xffffffffu, wsum, 16);

    if (eg == 0) {
        float inv = 1.0f / (wsum + 1e-15f);
        float o[8];
#pragma unroll
        for (int j = 0; j < 8; j++) {
            float hp = acc[j] * inv;
            o[j] = hp > 0.0f ? hp : expm1f(hp);
        }
        float* dst = out + (size_t)node * F_OUT + sub * 8;
        *(float4*)(dst)     = make_float4(o[0], o[1], o[2], o[3]);
        *(float4*)(dst + 4) = make_float4(o[4], o[5], o[6], o[7]);
    }
}

// ---------------------------------------------------------------------------
extern "C" void kernel_launch(void* const* d_in, const int* in_sizes, int n_in,
                              void* d_out, int out_size) {
    // Identify inputs by element count (robust to metadata ordering):
    //   inputs: 25,600,000   edge_index: 6,400,000   W: 16,384   a: 128
    int idx[4] = {0, 1, 2, 3};
    for (int i = 1; i < 4 && i < n_in; i++) {
        int k = idx[i], j = i - 1;
        while (j >= 0 && in_sizes[idx[j]] < in_sizes[k]) { idx[j + 1] = idx[j]; j--; }
        idx[j + 1] = k;
    }
    const float* X    = (const float*)d_in[idx[0]];
    const int*   ei32 = (const int*)d_in[idx[1]];
    const float* W    = (const float*)d_in[idx[2]];
    const float* a    = (const float*)d_in[idx[3]];
    float*       out  = (float*)d_out;

    int M = in_sizes[idx[0]] / F_IN;   // 100000
    int E = in_sizes[idx[1]] / 2;      // 3200000

    detect_kernel<<<1, 1>>>(ei32);
    zero_deg_kernel<<<(M + 255) / 256, 256>>>(M);
    gemm_kernel<<<(M + 127) / 128, 256>>>(X, W, M);
    s_kernel<<<(M * 32 + 255) / 256, 256>>>(a, M);

    hist_kernel<<<(E + 255) / 256, 256>>>(ei32, E, M);
    int nblk = (M + 1023) / 1024;
    scan1_kernel<<<nblk, 1024>>>(M);
    scan2_kernel<<<1, 128>>>(nblk);
    scan3_kernel<<<(M + 255) / 256, 256>>>(M);
    scatter_kernel<<<(E + 255) / 256, 256>>>(ei32, E, M);

    aggregate_kernel<<<(M * 32 + 255) / 256, 256>>>(out, M);
}

// round 5
// speedup vs baseline: 1.0466x; 1.0466x over previous
#include <cuda_runtime.h>
#include <cstdint>

#define F_IN 256
#define F_OUT 64
#define MAX_N 100000
#define MAX_E 3200000

// Scratch (device globals — no allocation allowed)
__device__ float g_h[(size_t)MAX_N * F_OUT];
__device__ float g_s1[MAX_N];
__device__ float g_s2[MAX_N];
__device__ int   g_deg[MAX_N];
__device__ int   g_rowptr[MAX_N + 1];
__device__ int   g_woff[MAX_N];
__device__ int   g_sdst[MAX_E];
__device__ int   g_bsum[128];
__device__ int   g_is64;

// ---------------------------------------------------------------------------
// Detect edge_index dtype: int64 (odd 32-bit words all zero) vs int32.
// ---------------------------------------------------------------------------
__global__ void detect_kernel(const int* __restrict__ ei32) {
    int is64 = 1;
    for (int i = 0; i < 64; i++)
        if (ei32[2 * i + 1] != 0) { is64 = 0; break; }
    g_is64 = is64;
}

__device__ __forceinline__ int edge_at(const int* ei32, int is64, long long idx) {
    return is64 ? ei32[2 * idx] : ei32[idx];   // little-endian low word
}

// ---------------------------------------------------------------------------
__global__ void zero_deg_kernel(int n) {
    int i = blockIdx.x * blockDim.x + threadIdx.x;
    if (i < n) g_deg[i] = 0;
}

// ---------------------------------------------------------------------------
// Packed f32x2 helpers (sm_100+ PTX; ptxas never auto-fuses FFMA2)
// ---------------------------------------------------------------------------
__device__ __forceinline__ unsigned long long pack_dup(float x) {
    unsigned long long r;
    unsigned u = __float_as_uint(x);
    asm("mov.b64 %0, {%1, %1};" : "=l"(r) : "r"(u));
    return r;
}
__device__ __forceinline__ void fma_f32x2(unsigned long long& acc,
                                          unsigned long long a,
                                          unsigned long long b) {
    asm("fma.rn.f32x2 %0, %1, %2, %0;" : "+l"(acc) : "l"(a), "l"(b));
}

// ---------------------------------------------------------------------------
// SGEMM: h[M,64] = X[M,256] @ W[256,64], fused s1/s2 = h@a1, h@a2 epilogue.
// Block: 128 rows x 64 cols, 256 threads, each thread 8 rows x 4 cols.
// Inner loop uses fma.rn.f32x2: rows packed in pairs (2x FMA throughput).
// ---------------------------------------------------------------------------
__global__ void gemm_kernel(const float* __restrict__ X, const float* __restrict__ W,
                            const float* __restrict__ a, int M) {
    __shared__ __align__(16) float Xs[32][132];
    __shared__ __align__(16) float Ws[32][64];

    int tid = threadIdx.x;
    int tx = tid & 15;   // col group: cols tx*4 .. tx*4+3
    int ty = tid >> 4;   // row group: rows ty*8 .. ty*8+7
    int m0 = blockIdx.x * 128;

    // accp[p][j]: packed rows (2p, 2p+1), column j
    unsigned long long accp[4][4];
#pragma unroll
    for (int p = 0; p < 4; p++)
#pragma unroll
        for (int j = 0; j < 4; j++) accp[p][j] = 0ull;

    for (int k0 = 0; k0 < F_IN; k0 += 32) {
#pragma unroll
        for (int i = 0; i < 4; i++) {
            int idx = tid + i * 256;
            int r   = idx >> 3;
            int kc  = idx & 7;
            float4 v = make_float4(0.f, 0.f, 0.f, 0.f);
            int row = m0 + r;
            if (row < M)
                v = *(const float4*)(X + (size_t)row * F_IN + k0 + kc * 4);
            Xs[kc * 4 + 0][r] = v.x;
            Xs[kc * 4 + 1][r] = v.y;
            Xs[kc * 4 + 2][r] = v.z;
            Xs[kc * 4 + 3][r] = v.w;
        }
#pragma unroll
        for (int i = 0; i < 2; i++) {
            int idx = tid + i * 256;
            int kr  = idx >> 4;
            int c4  = idx & 15;
            float4 w = *(const float4*)(W + (size_t)(k0 + kr) * F_OUT + c4 * 4);
            *(float4*)&Ws[kr][c4 * 4] = w;
        }
        __syncthreads();

#pragma unroll
        for (int kk = 0; kk < 32; kk++) {
            float4 b = *(const float4*)&Ws[kk][tx * 4];
            unsigned long long bv0 = pack_dup(b.x);
            unsigned long long bv1 = pack_dup(b.y);
            unsigned long long bv2 = pack_dup(b.z);
            unsigned long long bv3 = pack_dup(b.w);
            unsigned long long av[4];
#pragma unroll
            for (int p = 0; p < 4; p++)
                av[p] = *(const unsigned long long*)&Xs[kk][ty * 8 + 2 * p];
#pragma unroll
            for (int p = 0; p < 4; p++) {
                fma_f32x2(accp[p][0], av[p], bv0);
                fma_f32x2(accp[p][1], av[p], bv1);
                fma_f32x2(accp[p][2], av[p], bv2);
                fma_f32x2(accp[p][3], av[p], bv3);
            }
        }
        __syncthreads();
    }

    // Unpack accumulators: accf[i][j] = h[local row i][col tx*4+j]
    float accf[8][4];
#pragma unroll
    for (int p = 0; p < 4; p++)
#pragma unroll
        for (int j = 0; j < 4; j++) {
            float2 f = *reinterpret_cast<float2*>(&accp[p][j]);
            accf[2 * p][j]     = f.x;
            accf[2 * p + 1][j] = f.y;
        }

    // Store h
#pragma unroll
    for (int i = 0; i < 8; i++) {
        int row = m0 + ty * 8 + i;
        if (row < M)
            *(float4*)(g_h + (size_t)row * F_OUT + tx * 4) =
                make_float4(accf[i][0], accf[i][1], accf[i][2], accf[i][3]);
    }

    // Fused s1/s2 epilogue: dot each row with a1/a2 slice, reduce across tx
    float a1v[4], a2v[4];
#pragma unroll
    for (int j = 0; j < 4; j++) {
        a1v[j] = __ldg(a + tx * 4 + j);
        a2v[j] = __ldg(a + 64 + tx * 4 + j);
    }
    float s1p[8], s2p[8];
#pragma unroll
    for (int i = 0; i < 8; i++) {
        float t1 = 0.f, t2 = 0.f;
#pragma unroll
        for (int j = 0; j < 4; j++) {
            t1 = fmaf(accf[i][j], a1v[j], t1);
            t2 = fmaf(accf[i][j], a2v[j], t2);
        }
        s1p[i] = t1; s2p[i] = t2;
    }
    // xor-reduce over the 16 tx lanes (offsets 1,2,4,8 stay within half-warp)
#pragma unroll
    for (int o = 1; o < 16; o <<= 1) {
#pragma unroll
        for (int i = 0; i < 8; i++) {
            s1p[i] += __shfl_xor_sync(0xffffffffu, s1p[i], o);
            s2p[i] += __shfl_xor_sync(0xffffffffu, s2p[i], o);
        }
    }
    if (tx == 0) {
#pragma unroll
        for (int i = 0; i < 8; i++) {
            int row = m0 + ty * 8 + i;
            if (row < M) { g_s1[row] = s1p[i]; g_s2[row] = s2p[i]; }
        }
    }
}

// ---------------------------------------------------------------------------
// CSR build: histogram -> scan -> scatter  (src/dst bounds-guarded)
// ---------------------------------------------------------------------------
__global__ void hist_kernel(const int* __restrict__ ei32, int E, int M) {
    int e = blockIdx.x * blockDim.x + threadIdx.x;
    if (e >= E) return;
    int is64 = g_is64;
    int src = edge_at(ei32, is64, e);
    if ((unsigned)src < (unsigned)M) atomicAdd(&g_deg[src], 1);
}

__global__ void scan1_kernel(int n) {
    __shared__ int s[1024];
    int i = blockIdx.x * 1024 + threadIdx.x;
    int v = (i < n) ? g_deg[i] : 0;
    s[threadIdx.x] = v;
    __syncthreads();
#pragma unroll
    for (int o = 1; o < 1024; o <<= 1) {
        int t = (threadIdx.x >= o) ? s[threadIdx.x - o] : 0;
        __syncthreads();
        s[threadIdx.x] += t;
        __syncthreads();
    }
    if (i < n) g_rowptr[i + 1] = s[threadIdx.x];
    if (threadIdx.x == 1023) g_bsum[blockIdx.x] = s[1023];
}

__global__ void scan2_kernel(int nb) {
    __shared__ int s[128];
    int v = (threadIdx.x < nb) ? g_bsum[threadIdx.x] : 0;
    s[threadIdx.x] = v;
    __syncthreads();
#pragma unroll
    for (int o = 1; o < 128; o <<= 1) {
        int t = (threadIdx.x >= o) ? s[threadIdx.x - o] : 0;
        __syncthreads();
        s[threadIdx.x] += t;
        __syncthreads();
    }
    if (threadIdx.x < nb) g_bsum[threadIdx.x] = s[threadIdx.x] - v;
}

__global__ void scan3_kernel(int n) {
    int i = blockIdx.x * blockDim.x + threadIdx.x;
    if (i < n) {
        int val = g_rowptr[i + 1] + g_bsum[i >> 10];
        g_rowptr[i + 1] = val;
        g_woff[i] = val - g_deg[i];
    }
    if (i == 0) g_rowptr[0] = 0;
}

__global__ void scatter_kernel(const int* __restrict__ ei32, int E, int M) {
    int e = blockIdx.x * blockDim.x + threadIdx.x;
    if (e >= E) return;
    int is64 = g_is64;
    int src = edge_at(ei32, is64, e);
    int dst = edge_at(ei32, is64, (long long)E + e);
    if ((unsigned)src >= (unsigned)M || (unsigned)dst >= (unsigned)M) return;
    int pos = atomicAdd(&g_woff[src], 1);
    if ((unsigned)pos < (unsigned)MAX_E) g_sdst[pos] = dst;
}

// ---------------------------------------------------------------------------
// Aggregate + finalize: one warp per node. 8 lanes per edge (8 feats/lane),
// 4 edges in flight per warp. No atomics; fused rowsum-divide + ELU.
// w = exp(lrelu(s1[src]+s2[dst]))   (global-max subtraction cancels; skipped)
// ---------------------------------------------------------------------------
__global__ void aggregate_kernel(float* __restrict__ out, int M) {
    int node = (blockIdx.x * blockDim.x + threadIdx.x) >> 5;
    if (node >= M) return;
    int lane = threadIdx.x & 31;
    int sub  = lane & 7;    // feature group
    int eg   = lane >> 3;   // edge group 0..3

    int beg = g_rowptr[node];
    int end = g_rowptr[node + 1];
    float s1v = g_s1[node];

    float acc[8];
#pragma unroll
    for (int j = 0; j < 8; j++) acc[j] = 0.0f;
    float wsum = 0.0f;

    for (int p = beg + eg; p < end; p += 4) {
        int dst = g_sdst[p];
        float v  = s1v + g_s2[dst];
        float ev = v > 0.0f ? v : 0.2f * v;
        float w  = __expf(ev);
        wsum += w;

        const float4* hv = (const float4*)(g_h + (size_t)dst * F_OUT);
        float4 p0 = hv[sub * 2];
        float4 p1 = hv[sub * 2 + 1];
        acc[0] = fmaf(w, p0.x, acc[0]);
        acc[1] = fmaf(w, p0.y, acc[1]);
        acc[2] = fmaf(w, p0.z, acc[2]);
        acc[3] = fmaf(w, p0.w, acc[3]);
        acc[4] = fmaf(w, p1.x, acc[4]);
        acc[5] = fmaf(w, p1.y, acc[5]);
        acc[6] = fmaf(w, p1.z, acc[6]);
        acc[7] = fmaf(w, p1.w, acc[7]);
    }

#pragma unroll
    for (int j = 0; j < 8; j++) {
        acc[j] += __shfl_xor_sync(0xffffffffu, acc[j], 8);
        acc[j] += __shfl_xor_sync(0xffffffffu, acc[j], 16);
    }
    wsum += __shfl_xor_sync(0xffffffffu, wsum, 8);
    wsum += __shfl_xor_sync(0xffffffffu, wsum, 16);

    if (eg == 0) {
        float inv = 1.0f / (wsum + 1e-15f);
        float o[8];
#pragma unroll
        for (int j = 0; j < 8; j++) {
            float hp = acc[j] * inv;
            o[j] = hp > 0.0f ? hp : expm1f(hp);
        }
        float* dst = out + (size_t)node * F_OUT + sub * 8;
        *(float4*)(dst)     = make_float4(o[0], o[1], o[2], o[3]);
        *(float4*)(dst + 4) = make_float4(o[4], o[5], o[6], o[7]);
    }
}

// ---------------------------------------------------------------------------
extern "C" void kernel_launch(void* const* d_in, const int* in_sizes, int n_in,
                              void* d_out, int out_size) {
    // Identify inputs by element count (robust to metadata ordering)
    int idx[4] = {0, 1, 2, 3};
    for (int i = 1; i < 4 && i < n_in; i++) {
        int k = idx[i], j = i - 1;
        while (j >= 0 && in_sizes[idx[j]] < in_sizes[k]) { idx[j + 1] = idx[j]; j--; }
        idx[j + 1] = k;
    }
    const float* X    = (const float*)d_in[idx[0]];
    const int*   ei32 = (const int*)d_in[idx[1]];
    const float* W    = (const float*)d_in[idx[2]];
    const float* a    = (const float*)d_in[idx[3]];
    float*       out  = (float*)d_out;

    int M = in_sizes[idx[0]] / F_IN;   // 100000
    int E = in_sizes[idx[1]] / 2;      // 3200000

    detect_kernel<<<1, 1>>>(ei32);
    zero_deg_kernel<<<(M + 255) / 256, 256>>>(M);
    gemm_kernel<<<(M + 127) / 128, 256>>>(X, W, a, M);

    hist_kernel<<<(E + 255) / 256, 256>>>(ei32, E, M);
    int nblk = (M + 1023) / 1024;
    scan1_kernel<<<nblk, 1024>>>(M);
    scan2_kernel<<<1, 128>>>(nblk);
    scan3_kernel<<<(M + 255) / 256, 256>>>(M);
    scatter_kernel<<<(E + 255) / 256, 256>>>(ei32, E, M);

    aggregate_kernel<<<(M * 32 + 255) / 256, 256>>>(out, M);
}

// round 6
// speedup vs baseline: 1.0773x; 1.0293x over previous
#include <cuda_runtime.h>
#include <cuda_fp16.h>
#include <cstdint>

#define F_IN 256
#define F_OUT 64
#define MAX_N 100000
#define MAX_E 3200000

// Scratch (device globals — no allocation allowed)
__device__ __half g_h16[(size_t)MAX_N * F_OUT];
__device__ float  g_s1[MAX_N];
__device__ float  g_s2[MAX_N];
__device__ int    g_deg[MAX_N];
__device__ int    g_rowptr[MAX_N + 1];
__device__ int    g_rank[MAX_E];
__device__ int    g_sdst[MAX_E];
__device__ int    g_bsum[128];
__device__ int    g_is64;

// ---------------------------------------------------------------------------
// Detect edge_index dtype: int64 (odd 32-bit words all zero) vs int32.
// One warp, parallel loads + ballot (avoids serial DRAM latency chain).
// ---------------------------------------------------------------------------
__global__ void detect_kernel(const int* __restrict__ ei32) {
    int lane = threadIdx.x;
    int bad = 0;
    for (int i = lane; i < 64; i += 32)
        if (ei32[2 * i + 1] != 0) bad = 1;
    unsigned m = __ballot_sync(0xffffffffu, bad);
    if (lane == 0) g_is64 = (m == 0u);
}

__device__ __forceinline__ int edge_at(const int* ei32, int is64, long long idx) {
    return is64 ? ei32[2 * idx] : ei32[idx];   // little-endian low word
}

// ---------------------------------------------------------------------------
__global__ void zero_deg_kernel(int n) {
    int i = blockIdx.x * blockDim.x + threadIdx.x;
    if (i < n) g_deg[i] = 0;
}

// ---------------------------------------------------------------------------
// Packed f32x2 helpers (sm_100+ PTX; ptxas never auto-fuses FFMA2)
// ---------------------------------------------------------------------------
__device__ __forceinline__ unsigned long long pack_dup(float x) {
    unsigned long long r;
    unsigned u = __float_as_uint(x);
    asm("mov.b64 %0, {%1, %1};" : "=l"(r) : "r"(u));
    return r;
}
__device__ __forceinline__ void fma_f32x2(unsigned long long& acc,
                                          unsigned long long a,
                                          unsigned long long b) {
    asm("fma.rn.f32x2 %0, %1, %2, %0;" : "+l"(acc) : "l"(a), "l"(b));
}

// ---------------------------------------------------------------------------
// SGEMM: h[M,64] = X[M,256] @ W[256,64], fused s1/s2 epilogue.
// h stored as fp16 (halves aggregate gather traffic); s1/s2 from fp32 accs.
// ---------------------------------------------------------------------------
__global__ void gemm_kernel(const float* __restrict__ X, const float* __restrict__ W,
                            const float* __restrict__ a, int M) {
    __shared__ __align__(16) float Xs[32][132];
    __shared__ __align__(16) float Ws[32][64];

    int tid = threadIdx.x;
    int tx = tid & 15;   // col group: cols tx*4 .. tx*4+3
    int ty = tid >> 4;   // row group: rows ty*8 .. ty*8+7
    int m0 = blockIdx.x * 128;

    unsigned long long accp[4][4];
#pragma unroll
    for (int p = 0; p < 4; p++)
#pragma unroll
        for (int j = 0; j < 4; j++) accp[p][j] = 0ull;

    for (int k0 = 0; k0 < F_IN; k0 += 32) {
#pragma unroll
        for (int i = 0; i < 4; i++) {
            int idx = tid + i * 256;
            int r   = idx >> 3;
            int kc  = idx & 7;
            float4 v = make_float4(0.f, 0.f, 0.f, 0.f);
            int row = m0 + r;
            if (row < M)
                v = *(const float4*)(X + (size_t)row * F_IN + k0 + kc * 4);
            Xs[kc * 4 + 0][r] = v.x;
            Xs[kc * 4 + 1][r] = v.y;
            Xs[kc * 4 + 2][r] = v.z;
            Xs[kc * 4 + 3][r] = v.w;
        }
#pragma unroll
        for (int i = 0; i < 2; i++) {
            int idx = tid + i * 256;
            int kr  = idx >> 4;
            int c4  = idx & 15;
            float4 w = *(const float4*)(W + (size_t)(k0 + kr) * F_OUT + c4 * 4);
            *(float4*)&Ws[kr][c4 * 4] = w;
        }
        __syncthreads();

#pragma unroll
        for (int kk = 0; kk < 32; kk++) {
            float4 b = *(const float4*)&Ws[kk][tx * 4];
            unsigned long long bv0 = pack_dup(b.x);
            unsigned long long bv1 = pack_dup(b.y);
            unsigned long long bv2 = pack_dup(b.z);
            unsigned long long bv3 = pack_dup(b.w);
            unsigned long long av[4];
#pragma unroll
            for (int p = 0; p < 4; p++)
                av[p] = *(const unsigned long long*)&Xs[kk][ty * 8 + 2 * p];
#pragma unroll
            for (int p = 0; p < 4; p++) {
                fma_f32x2(accp[p][0], av[p], bv0);
                fma_f32x2(accp[p][1], av[p], bv1);
                fma_f32x2(accp[p][2], av[p], bv2);
                fma_f32x2(accp[p][3], av[p], bv3);
            }
        }
        __syncthreads();
    }

    float accf[8][4];
#pragma unroll
    for (int p = 0; p < 4; p++)
#pragma unroll
        for (int j = 0; j < 4; j++) {
            float2 f = *reinterpret_cast<float2*>(&accp[p][j]);
            accf[2 * p][j]     = f.x;
            accf[2 * p + 1][j] = f.y;
        }

    // Store h as fp16: 4 cols -> 2 half2 -> 8B per row-segment
#pragma unroll
    for (int i = 0; i < 8; i++) {
        int row = m0 + ty * 8 + i;
        if (row < M) {
            __half2 lo = __floats2half2_rn(accf[i][0], accf[i][1]);
            __half2 hi = __floats2half2_rn(accf[i][2], accf[i][3]);
            uint2 pkt = make_uint2(*(unsigned*)&lo, *(unsigned*)&hi);
            *(uint2*)(g_h16 + (size_t)row * F_OUT + tx * 4) = pkt;
        }
    }

    // Fused s1/s2 epilogue (fp32, exact)
    float a1v[4], a2v[4];
#pragma unroll
    for (int j = 0; j < 4; j++) {
        a1v[j] = __ldg(a + tx * 4 + j);
        a2v[j] = __ldg(a + 64 + tx * 4 + j);
    }
    float s1p[8], s2p[8];
#pragma unroll
    for (int i = 0; i < 8; i++) {
        float t1 = 0.f, t2 = 0.f;
#pragma unroll
        for (int j = 0; j < 4; j++) {
            t1 = fmaf(accf[i][j], a1v[j], t1);
            t2 = fmaf(accf[i][j], a2v[j], t2);
        }
        s1p[i] = t1; s2p[i] = t2;
    }
#pragma unroll
    for (int o = 1; o < 16; o <<= 1) {
#pragma unroll
        for (int i = 0; i < 8; i++) {
            s1p[i] += __shfl_xor_sync(0xffffffffu, s1p[i], o);
            s2p[i] += __shfl_xor_sync(0xffffffffu, s2p[i], o);
        }
    }
    if (tx == 0) {
#pragma unroll
        for (int i = 0; i < 8; i++) {
            int row = m0 + ty * 8 + i;
            if (row < M) { g_s1[row] = s1p[i]; g_s2[row] = s2p[i]; }
        }
    }
}

// ---------------------------------------------------------------------------
// CSR build: rank (atomic) -> scan -> scatter (plain store, no atomics)
// ---------------------------------------------------------------------------
__global__ void rank_kernel(const int* __restrict__ ei32, int E, int M) {
    int e = blockIdx.x * blockDim.x + threadIdx.x;
    if (e >= E) return;
    int is64 = g_is64;
    int src = edge_at(ei32, is64, e);
    int dst = edge_at(ei32, is64, (long long)E + e);
    int r = -1;
    if ((unsigned)src < (unsigned)M && (unsigned)dst < (unsigned)M)
        r = atomicAdd(&g_deg[src], 1);
    g_rank[e] = r;
}

__global__ void scan1_kernel(int n) {
    __shared__ int s[1024];
    int i = blockIdx.x * 1024 + threadIdx.x;
    int v = (i < n) ? g_deg[i] : 0;
    s[threadIdx.x] = v;
    __syncthreads();
#pragma unroll
    for (int o = 1; o < 1024; o <<= 1) {
        int t = (threadIdx.x >= o) ? s[threadIdx.x - o] : 0;
        __syncthreads();
        s[threadIdx.x] += t;
        __syncthreads();
    }
    if (i < n) g_rowptr[i + 1] = s[threadIdx.x];
    if (threadIdx.x == 1023) g_bsum[blockIdx.x] = s[1023];
}

__global__ void scan2_kernel(int nb) {
    __shared__ int s[128];
    int v = (threadIdx.x < nb) ? g_bsum[threadIdx.x] : 0;
    s[threadIdx.x] = v;
    __syncthreads();
#pragma unroll
    for (int o = 1; o < 128; o <<= 1) {
        int t = (threadIdx.x >= o) ? s[threadIdx.x - o] : 0;
        __syncthreads();
        s[threadIdx.x] += t;
        __syncthreads();
    }
    if (threadIdx.x < nb) g_bsum[threadIdx.x] = s[threadIdx.x] - v;
}

__global__ void scan3_kernel(int n) {
    int i = blockIdx.x * blockDim.x + threadIdx.x;
    if (i < n) g_rowptr[i + 1] += g_bsum[i >> 10];
    if (i == 0) g_rowptr[0] = 0;
}

__global__ void scatter_kernel(const int* __restrict__ ei32, int E, int M) {
    int e = blockIdx.x * blockDim.x + threadIdx.x;
    if (e >= E) return;
    int r = g_rank[e];
    if (r < 0) return;
    int is64 = g_is64;
    int src = edge_at(ei32, is64, e);
    int dst = edge_at(ei32, is64, (long long)E + e);
    g_sdst[g_rowptr[src] + r] = dst;
}

// ---------------------------------------------------------------------------
// Aggregate + finalize: one warp per node. 8 lanes per edge (8 feats/lane),
// 4 edges in flight. fp16 h gathers (16B/lane/edge); fp32 accumulate.
// w = exp(lrelu(s1[src]+s2[dst]))   (global-max subtraction cancels; skipped)
// ---------------------------------------------------------------------------
__global__ void aggregate_kernel(float* __restrict__ out, int M) {
    int node = (blockIdx.x * blockDim.x + threadIdx.x) >> 5;
    if (node >= M) return;
    int lane = threadIdx.x & 31;
    int sub  = lane & 7;    // feature group: features sub*8 .. sub*8+7
    int eg   = lane >> 3;   // edge group 0..3

    int beg = g_rowptr[node];
    int end = g_rowptr[node + 1];
    float s1v = g_s1[node];

    float acc[8];
#pragma unroll
    for (int j = 0; j < 8; j++) acc[j] = 0.0f;
    float wsum = 0.0f;

    for (int p = beg + eg; p < end; p += 4) {
        int dst = g_sdst[p];
        float v  = s1v + g_s2[dst];
        float ev = v > 0.0f ? v : 0.2f * v;
        float w  = __expf(ev);
        wsum += w;

        // 16B = 8 halves = this lane's 8 features of h[dst]
        uint4 q = *(const uint4*)(g_h16 + (size_t)dst * F_OUT + sub * 8);
        float2 f0 = __half22float2(*(const __half2*)&q.x);
        float2 f1 = __half22float2(*(const __half2*)&q.y);
        float2 f2 = __half22float2(*(const __half2*)&q.z);
        float2 f3 = __half22float2(*(const __half2*)&q.w);
        acc[0] = fmaf(w, f0.x, acc[0]);
        acc[1] = fmaf(w, f0.y, acc[1]);
        acc[2] = fmaf(w, f1.x, acc[2]);
        acc[3] = fmaf(w, f1.y, acc[3]);
        acc[4] = fmaf(w, f2.x, acc[4]);
        acc[5] = fmaf(w, f2.y, acc[5]);
        acc[6] = fmaf(w, f3.x, acc[6]);
        acc[7] = fmaf(w, f3.y, acc[7]);
    }

#pragma unroll
    for (int j = 0; j < 8; j++) {
        acc[j] += __shfl_xor_sync(0xffffffffu, acc[j], 8);
        acc[j] += __shfl_xor_sync(0xffffffffu, acc[j], 16);
    }
    wsum += __shfl_xor_sync(0xffffffffu, wsum, 8);
    wsum += __shfl_xor_sync(0xffffffffu, wsum, 16);

    if (eg == 0) {
        float inv = 1.0f / (wsum + 1e-15f);
        float o[8];
#pragma unroll
        for (int j = 0; j < 8; j++) {
            float hp = acc[j] * inv;
            o[j] = hp > 0.0f ? hp : expm1f(hp);
        }
        float* dst = out + (size_t)node * F_OUT + sub * 8;
        *(float4*)(dst)     = make_float4(o[0], o[1], o[2], o[3]);
        *(float4*)(dst + 4) = make_float4(o[4], o[5], o[6], o[7]);
    }
}

// ---------------------------------------------------------------------------
extern "C" void kernel_launch(void* const* d_in, const int* in_sizes, int n_in,
                              void* d_out, int out_size) {
    // Identify inputs by element count (robust to metadata ordering)
    int idx[4] = {0, 1, 2, 3};
    for (int i = 1; i < 4 && i < n_in; i++) {
        int k = idx[i], j = i - 1;
        while (j >= 0 && in_sizes[idx[j]] < in_sizes[k]) { idx[j + 1] = idx[j]; j--; }
        idx[j + 1] = k;
    }
    const float* X    = (const float*)d_in[idx[0]];
    const int*   ei32 = (const int*)d_in[idx[1]];
    const float* W    = (const float*)d_in[idx[2]];
    const float* a    = (const float*)d_in[idx[3]];
    float*       out  = (float*)d_out;

    int M = in_sizes[idx[0]] / F_IN;   // 100000
    int E = in_sizes[idx[1]] / 2;      // 3200000

    detect_kernel<<<1, 32>>>(ei32);
    zero_deg_kernel<<<(M + 511) / 512, 512>>>(M);
    gemm_kernel<<<(M + 127) / 128, 256>>>(X, W, a, M);

    rank_kernel<<<(E + 255) / 256, 256>>>(ei32, E, M);
    int nblk = (M + 1023) / 1024;
    scan1_kernel<<<nblk, 1024>>>(M);
    scan2_kernel<<<1, 128>>>(nblk);
    scan3_kernel<<<(M + 255) / 256, 256>>>(M);
    scatter_kernel<<<(E + 255) / 256, 256>>>(ei32, E, M);

    aggregate_kernel<<<(M * 32 + 255) / 256, 256>>>(out, M);
}

// round 7
// speedup vs baseline: 1.1586x; 1.0755x over previous
#include <cuda_runtime.h>
#include <cuda_fp16.h>
#include <cstdint>

#define F_IN 256
#define F_OUT 64
#define MAX_N 100000
#define MAX_E 3200000

// Scratch (device globals — no allocation allowed)
__device__ __half g_h16[(size_t)MAX_N * F_OUT];
__device__ float  g_s1[MAX_N];
__device__ float  g_s2[MAX_N];
__device__ int    g_deg[MAX_N];
__device__ int    g_rowptr[MAX_N + 1];
__device__ int    g_rank[MAX_E];
__device__ int    g_sdst[MAX_E];
__device__ int    g_bsum[128];
__device__ int    g_is64;

// ---------------------------------------------------------------------------
// Detect edge_index dtype: int64 (odd 32-bit words all zero) vs int32.
// ---------------------------------------------------------------------------
__global__ void detect_kernel(const int* __restrict__ ei32) {
    int lane = threadIdx.x;
    int bad = 0;
    for (int i = lane; i < 64; i += 32)
        if (ei32[2 * i + 1] != 0) bad = 1;
    unsigned m = __ballot_sync(0xffffffffu, bad);
    if (lane == 0) g_is64 = (m == 0u);
}

__device__ __forceinline__ int edge_at(const int* ei32, int is64, long long idx) {
    return is64 ? ei32[2 * idx] : ei32[idx];   // little-endian low word
}

// ---------------------------------------------------------------------------
__global__ void zero_deg_kernel(int n) {
    int i = blockIdx.x * blockDim.x + threadIdx.x;
    if (i < n) g_deg[i] = 0;
}

// ---------------------------------------------------------------------------
// Packed f32x2 helpers (sm_100+ PTX; ptxas never auto-fuses FFMA2)
// ---------------------------------------------------------------------------
__device__ __forceinline__ unsigned long long pack_dup(float x) {
    unsigned long long r;
    unsigned u = __float_as_uint(x);
    asm("mov.b64 %0, {%1, %1};" : "=l"(r) : "r"(u));
    return r;
}
__device__ __forceinline__ void fma_f32x2(unsigned long long& acc,
                                          unsigned long long a,
                                          unsigned long long b) {
    asm("fma.rn.f32x2 %0, %1, %2, %0;" : "+l"(acc) : "l"(a), "l"(b));
}

// ---------------------------------------------------------------------------
// FUSED kernel: blocks [0, gemmBlocks) run the SGEMM (+s1/s2 epilogue);
// blocks [gemmBlocks, ...) run the edge-rank pass (histogram + rank).
// The two are independent and stress opposite resources (FMA vs L2 atomics),
// so co-residency hides the rank pass almost entirely.
// ---------------------------------------------------------------------------
__global__ __launch_bounds__(256) void gemm_rank_kernel(
    const float* __restrict__ X, const float* __restrict__ W,
    const float* __restrict__ a, const int* __restrict__ ei32,
    int M, int E, int gemmBlocks)
{
    __shared__ __align__(16) float Xs[32][132];
    __shared__ __align__(16) float Ws[32][64];

    if (blockIdx.x >= gemmBlocks) {
        // ---- rank path ----
        int e = (blockIdx.x - gemmBlocks) * 256 + threadIdx.x;
        if (e >= E) return;
        int is64 = g_is64;
        int src = edge_at(ei32, is64, e);
        int dst = edge_at(ei32, is64, (long long)E + e);
        int r = -1;
        if ((unsigned)src < (unsigned)M && (unsigned)dst < (unsigned)M)
            r = atomicAdd(&g_deg[src], 1);
        g_rank[e] = r;
        return;
    }

    // ---- gemm path ----
    int tid = threadIdx.x;
    int tx = tid & 15;   // col group: cols tx*4 .. tx*4+3
    int ty = tid >> 4;   // row group: rows ty*8 .. ty*8+7
    int m0 = blockIdx.x * 128;

    unsigned long long accp[4][4];
#pragma unroll
    for (int p = 0; p < 4; p++)
#pragma unroll
        for (int j = 0; j < 4; j++) accp[p][j] = 0ull;

    for (int k0 = 0; k0 < F_IN; k0 += 32) {
#pragma unroll
        for (int i = 0; i < 4; i++) {
            int idx = tid + i * 256;
            int r   = idx >> 3;
            int kc  = idx & 7;
            float4 v = make_float4(0.f, 0.f, 0.f, 0.f);
            int row = m0 + r;
            if (row < M)
                v = *(const float4*)(X + (size_t)row * F_IN + k0 + kc * 4);
            Xs[kc * 4 + 0][r] = v.x;
            Xs[kc * 4 + 1][r] = v.y;
            Xs[kc * 4 + 2][r] = v.z;
            Xs[kc * 4 + 3][r] = v.w;
        }
#pragma unroll
        for (int i = 0; i < 2; i++) {
            int idx = tid + i * 256;
            int kr  = idx >> 4;
            int c4  = idx & 15;
            float4 w = *(const float4*)(W + (size_t)(k0 + kr) * F_OUT + c4 * 4);
            *(float4*)&Ws[kr][c4 * 4] = w;
        }
        __syncthreads();

#pragma unroll
        for (int kk = 0; kk < 32; kk++) {
            float4 b = *(const float4*)&Ws[kk][tx * 4];
            unsigned long long bv0 = pack_dup(b.x);
            unsigned long long bv1 = pack_dup(b.y);
            unsigned long long bv2 = pack_dup(b.z);
            unsigned long long bv3 = pack_dup(b.w);
            unsigned long long av[4];
#pragma unroll
            for (int p = 0; p < 4; p++)
                av[p] = *(const unsigned long long*)&Xs[kk][ty * 8 + 2 * p];
#pragma unroll
            for (int p = 0; p < 4; p++) {
                fma_f32x2(accp[p][0], av[p], bv0);
                fma_f32x2(accp[p][1], av[p], bv1);
                fma_f32x2(accp[p][2], av[p], bv2);
                fma_f32x2(accp[p][3], av[p], bv3);
            }
        }
        __syncthreads();
    }

    float accf[8][4];
#pragma unroll
    for (int p = 0; p < 4; p++)
#pragma unroll
        for (int j = 0; j < 4; j++) {
            float2 f = *reinterpret_cast<float2*>(&accp[p][j]);
            accf[2 * p][j]     = f.x;
            accf[2 * p + 1][j] = f.y;
        }

    // Store h as fp16
#pragma unroll
    for (int i = 0; i < 8; i++) {
        int row = m0 + ty * 8 + i;
        if (row < M) {
            __half2 lo = __floats2half2_rn(accf[i][0], accf[i][1]);
            __half2 hi = __floats2half2_rn(accf[i][2], accf[i][3]);
            uint2 pkt = make_uint2(*(unsigned*)&lo, *(unsigned*)&hi);
            *(uint2*)(g_h16 + (size_t)row * F_OUT + tx * 4) = pkt;
        }
    }

    // Fused s1/s2 epilogue (fp32, exact)
    float a1v[4], a2v[4];
#pragma unroll
    for (int j = 0; j < 4; j++) {
        a1v[j] = __ldg(a + tx * 4 + j);
        a2v[j] = __ldg(a + 64 + tx * 4 + j);
    }
    float s1p[8], s2p[8];
#pragma unroll
    for (int i = 0; i < 8; i++) {
        float t1 = 0.f, t2 = 0.f;
#pragma unroll
        for (int j = 0; j < 4; j++) {
            t1 = fmaf(accf[i][j], a1v[j], t1);
            t2 = fmaf(accf[i][j], a2v[j], t2);
        }
        s1p[i] = t1; s2p[i] = t2;
    }
#pragma unroll
    for (int o = 1; o < 16; o <<= 1) {
#pragma unroll
        for (int i = 0; i < 8; i++) {
            s1p[i] += __shfl_xor_sync(0xffffffffu, s1p[i], o);
            s2p[i] += __shfl_xor_sync(0xffffffffu, s2p[i], o);
        }
    }
    if (tx == 0) {
#pragma unroll
        for (int i = 0; i < 8; i++) {
            int row = m0 + ty * 8 + i;
            if (row < M) { g_s1[row] = s1p[i]; g_s2[row] = s2p[i]; }
        }
    }
}

// ---------------------------------------------------------------------------
// Scan (rowptr from deg), then atomic-free scatter using precomputed ranks
// ---------------------------------------------------------------------------
__global__ void scan1_kernel(int n) {
    __shared__ int s[1024];
    int i = blockIdx.x * 1024 + threadIdx.x;
    int v = (i < n) ? g_deg[i] : 0;
    s[threadIdx.x] = v;
    __syncthreads();
#pragma unroll
    for (int o = 1; o < 1024; o <<= 1) {
        int t = (threadIdx.x >= o) ? s[threadIdx.x - o] : 0;
        __syncthreads();
        s[threadIdx.x] += t;
        __syncthreads();
    }
    if (i < n) g_rowptr[i + 1] = s[threadIdx.x];
    if (threadIdx.x == 1023) g_bsum[blockIdx.x] = s[1023];
}

__global__ void scan2_kernel(int nb) {
    __shared__ int s[128];
    int v = (threadIdx.x < nb) ? g_bsum[threadIdx.x] : 0;
    s[threadIdx.x] = v;
    __syncthreads();
#pragma unroll
    for (int o = 1; o < 128; o <<= 1) {
        int t = (threadIdx.x >= o) ? s[threadIdx.x - o] : 0;
        __syncthreads();
        s[threadIdx.x] += t;
        __syncthreads();
    }
    if (threadIdx.x < nb) g_bsum[threadIdx.x] = s[threadIdx.x] - v;
}

__global__ void scan3_kernel(int n) {
    int i = blockIdx.x * blockDim.x + threadIdx.x;
    if (i < n) g_rowptr[i + 1] += g_bsum[i >> 10];
    if (i == 0) g_rowptr[0] = 0;
}

__global__ void scatter_kernel(const int* __restrict__ ei32, int E, int M) {
    int e = blockIdx.x * blockDim.x + threadIdx.x;
    if (e >= E) return;
    int r = g_rank[e];
    if (r < 0) return;
    int is64 = g_is64;
    int src = edge_at(ei32, is64, e);
    int dst = edge_at(ei32, is64, (long long)E + e);
    g_sdst[g_rowptr[src] + r] = dst;
}

// ---------------------------------------------------------------------------
// Aggregate + finalize: one warp per node, 4 edges in flight (eg groups),
// 8 feats/lane. Software-pipelined: prefetch next sdst before consuming
// current gathers (breaks the sdst->gather serial L2 chain).
// w = exp(lrelu(s1[src]+s2[dst]))   (global-max subtraction cancels; skipped)
// ---------------------------------------------------------------------------
__global__ void aggregate_kernel(float* __restrict__ out, int M) {
    int node = (blockIdx.x * blockDim.x + threadIdx.x) >> 5;
    if (node >= M) return;
    int lane = threadIdx.x & 31;
    int sub  = lane & 7;    // feature group: features sub*8 .. sub*8+7
    int eg   = lane >> 3;   // edge group 0..3

    int beg = g_rowptr[node];
    int end = g_rowptr[node + 1];
    float s1v = g_s1[node];

    float acc[8];
#pragma unroll
    for (int j = 0; j < 8; j++) acc[j] = 0.0f;
    float wsum = 0.0f;

    int p = beg + eg;
    int dst_cur = (p < end) ? g_sdst[p] : 0;
    for (; p < end; p += 4) {
        int pn = p + 4;
        int dst_next = (pn < end) ? g_sdst[pn] : 0;   // prefetch (independent)

        float s2v = g_s2[dst_cur];
        uint4 q = *(const uint4*)(g_h16 + (size_t)dst_cur * F_OUT + sub * 8);

        float v  = s1v + s2v;
        float ev = v > 0.0f ? v : 0.2f * v;
        float w  = __expf(ev);
        wsum += w;

        float2 f0 = __half22float2(*(const __half2*)&q.x);
        float2 f1 = __half22float2(*(const __half2*)&q.y);
        float2 f2 = __half22float2(*(const __half2*)&q.z);
        float2 f3 = __half22float2(*(const __half2*)&q.w);
        acc[0] = fmaf(w, f0.x, acc[0]);
        acc[1] = fmaf(w, f0.y, acc[1]);
        acc[2] = fmaf(w, f1.x, acc[2]);
        acc[3] = fmaf(w, f1.y, acc[3]);
        acc[4] = fmaf(w, f2.x, acc[4]);
        acc[5] = fmaf(w, f2.y, acc[5]);
        acc[6] = fmaf(w, f3.x, acc[6]);
        acc[7] = fmaf(w, f3.y, acc[7]);

        dst_cur = dst_next;
    }

#pragma unroll
    for (int j = 0; j < 8; j++) {
        acc[j] += __shfl_xor_sync(0xffffffffu, acc[j], 8);
        acc[j] += __shfl_xor_sync(0xffffffffu, acc[j], 16);
    }
    wsum += __shfl_xor_sync(0xffffffffu, wsum, 8);
    wsum += __shfl_xor_sync(0xffffffffu, wsum, 16);

    if (eg == 0) {
        float inv = 1.0f / (wsum + 1e-15f);
        float o[8];
#pragma unroll
        for (int j = 0; j < 8; j++) {
            float hp = acc[j] * inv;
            o[j] = hp > 0.0f ? hp : expm1f(hp);
        }
        float* dst = out + (size_t)node * F_OUT + sub * 8;
        *(float4*)(dst)     = make_float4(o[0], o[1], o[2], o[3]);
        *(float4*)(dst + 4) = make_float4(o[4], o[5], o[6], o[7]);
    }
}

// ---------------------------------------------------------------------------
extern "C" void kernel_launch(void* const* d_in, const int* in_sizes, int n_in,
                              void* d_out, int out_size) {
    // Identify inputs by element count (robust to metadata ordering)
    int idx[4] = {0, 1, 2, 3};
    for (int i = 1; i < 4 && i < n_in; i++) {
        int k = idx[i], j = i - 1;
        while (j >= 0 && in_sizes[idx[j]] < in_sizes[k]) { idx[j + 1] = idx[j]; j--; }
        idx[j + 1] = k;
    }
    const float* X    = (const float*)d_in[idx[0]];
    const int*   ei32 = (const int*)d_in[idx[1]];
    const float* W    = (const float*)d_in[idx[2]];
    const float* a    = (const float*)d_in[idx[3]];
    float*       out  = (float*)d_out;

    int M = in_sizes[idx[0]] / F_IN;   // 100000
    int E = in_sizes[idx[1]] / 2;      // 3200000

    detect_kernel<<<1, 32>>>(ei32);
    zero_deg_kernel<<<(M + 511) / 512, 512>>>(M);

    int gemmBlocks = (M + 127) / 128;
    int rankBlocks = (E + 255) / 256;
    gemm_rank_kernel<<<gemmBlocks + rankBlocks, 256>>>(X, W, a, ei32, M, E, gemmBlocks);

    int nblk = (M + 1023) / 1024;
    scan1_kernel<<<nblk, 1024>>>(M);
    scan2_kernel<<<1, 128>>>(nblk);
    scan3_kernel<<<(M + 255) / 256, 256>>>(M);
    scatter_kernel<<<(E + 255) / 256, 256>>>(ei32, E, M);

    aggregate_kernel<<<(M * 32 + 255) / 256, 256>>>(out, M);
}